// round 1
// baseline (speedup 1.0000x reference)
#include <cuda_runtime.h>
#include <cstdint>

#define N_NODES 50000
#define N_EDGES 640000
#define F 128

// Scratch (device globals — no runtime allocation allowed)
__device__ __align__(256) float g_summed[(size_t)N_NODES * F];   // 25.6 MB
__device__ __align__(256) float g_counts[N_NODES];
__device__ int g_idx64;

// ---------------------------------------------------------------------------
// Detect whether edge_index is int64 or int32 (JAX demotes int64->int32 unless
// x64 is enabled; we cannot see metadata, so probe the bit pattern).
// If the buffer is int64, words at odd int32 positions (high words) are all 0.
// If int32, those words are node indices in [0, 50000) — all-zero is ~impossible.
// Deterministic for a fixed input.
// ---------------------------------------------------------------------------
__global__ void detect_kernel(const int* __restrict__ e) {
    if (threadIdx.x == 0) {
        int nz = 0;
        #pragma unroll 8
        for (int i = 0; i < 256; i++) nz |= e[2 * i + 1];
        g_idx64 = (nz == 0) ? 1 : 0;
    }
}

// Zero the accumulators. 6.4M floats as 1.6M float4 (one per thread).
__global__ void zero_kernel() {
    int i = blockIdx.x * blockDim.x + threadIdx.x;   // 0 .. 1,599,999
    ((float4*)g_summed)[i] = make_float4(0.f, 0.f, 0.f, 0.f);
    if (i < N_NODES) g_counts[i] = 0.f;
}

// ---------------------------------------------------------------------------
// Scatter: one warp per edge. Each lane moves one float4 (32 lanes * 16B = 512B
// = one 128-float row). Scatter-add uses vectorized red.global.add.v4.f32
// (no return value -> REDG path, 4x fewer L2 atomic ops than scalar atomicAdd).
// x and g_summed are both L2-resident (25.6 MB each, 126 MB L2).
// ---------------------------------------------------------------------------
__global__ void __launch_bounds__(256) scatter_kernel(const void* __restrict__ eidx,
                                                      const float* __restrict__ x) {
    int warp = (blockIdx.x * 256 + threadIdx.x) >> 5;
    int lane = threadIdx.x & 31;
    if (warp >= N_EDGES) return;

    int src, dst;
    if (g_idx64) {
        const long long* e = (const long long*)eidx;
        src = (int)e[warp];
        dst = (int)e[N_EDGES + warp];
    } else {
        const int* e = (const int*)eidx;
        src = e[warp];
        dst = e[N_EDGES + warp];
    }

    float4 v = ((const float4*)(x + (size_t)src * F))[lane];
    float* p = g_summed + (size_t)dst * F + lane * 4;
    asm volatile("red.global.add.v4.f32 [%0], {%1,%2,%3,%4};"
                 :: "l"(p), "f"(v.x), "f"(v.y), "f"(v.z), "f"(v.w)
                 : "memory");
    if (lane == 0) atomicAdd(&g_counts[dst], 1.0f);
}

// ---------------------------------------------------------------------------
// Fused epilogue GEMM: out = relu(mean @ W_l + x @ W_r + b)
//   - W_l and W_r fully resident in smem (64 KB each)
//   - 64-row tile of mean (=summed*inv_count) and x staged in smem
//   - 512 threads: col = tid&127, row-group = tid>>7, 16 accumulators/thread
//   - float2 A/B smem loads (broadcast within warp), W loads coalesced
// ---------------------------------------------------------------------------
#define GEMM_ROWS 64
#define GEMM_THREADS 512
#define GEMM_SMEM (size_t)((16384 + 16384 + GEMM_ROWS * F * 2) * sizeof(float))  // 196608 B

extern __shared__ float smem[];

__global__ void __launch_bounds__(GEMM_THREADS) gemm_kernel(
    const float* __restrict__ x,
    const float* __restrict__ Wl,
    const float* __restrict__ Wr,
    const float* __restrict__ b,
    float* __restrict__ out)
{
    float* sWl = smem;                       // [128][128]
    float* sWr = smem + 16384;               // [128][128]
    float* sA  = smem + 32768;               // [64][128]  mean tile
    float* sB  = smem + 32768 + GEMM_ROWS*F; // [64][128]  x tile
    __shared__ float sInv[GEMM_ROWS];

    const int tid  = threadIdx.x;
    const int row0 = blockIdx.x * GEMM_ROWS;

    // Stage W (float4 copies)
    {
        const float4* wl4 = (const float4*)Wl;
        const float4* wr4 = (const float4*)Wr;
        float4* sl4 = (float4*)sWl;
        float4* sr4 = (float4*)sWr;
        #pragma unroll
        for (int i = tid; i < 4096; i += GEMM_THREADS) { sl4[i] = wl4[i]; sr4[i] = wr4[i]; }
    }
    if (tid < GEMM_ROWS) {
        int gr = row0 + tid;
        float c = (gr < N_NODES) ? g_counts[gr] : 1.f;
        sInv[tid] = 1.f / fmaxf(c, 1.f);
    }
    __syncthreads();

    // Stage A (mean) and B (x) tiles
    {
        float4* sa4 = (float4*)sA;
        float4* sb4 = (float4*)sB;
        #pragma unroll
        for (int i = tid; i < GEMM_ROWS * F / 4; i += GEMM_THREADS) {
            int r  = i >> 5;          // F/4 = 32 float4 per row
            int c4 = i & 31;
            int gr = row0 + r;
            float4 s, xv;
            if (gr < N_NODES) {
                s  = ((const float4*)g_summed)[(size_t)gr * 32 + c4];
                xv = ((const float4*)x)[(size_t)gr * 32 + c4];
            } else {
                s  = make_float4(0.f, 0.f, 0.f, 0.f);
                xv = s;
            }
            float inv = sInv[r];
            s.x *= inv; s.y *= inv; s.z *= inv; s.w *= inv;
            sa4[i] = s;
            sb4[i] = xv;
        }
    }
    __syncthreads();

    const int col   = tid & 127;
    const int rg    = tid >> 7;    // 0..3
    const int rbase = rg * 16;

    float acc[16];
    const float bias = b[col];
    #pragma unroll
    for (int i = 0; i < 16; i++) acc[i] = bias;

    #pragma unroll 2
    for (int k = 0; k < F; k += 2) {
        float wl0 = sWl[k * F + col];
        float wl1 = sWl[(k + 1) * F + col];
        float wr0 = sWr[k * F + col];
        float wr1 = sWr[(k + 1) * F + col];
        #pragma unroll
        for (int i = 0; i < 16; i++) {
            float2 a  = *(const float2*)&sA[(rbase + i) * F + k];
            float2 xx = *(const float2*)&sB[(rbase + i) * F + k];
            acc[i] += a.x * wl0 + xx.x * wr0;
            acc[i] += a.y * wl1 + xx.y * wr1;
        }
    }

    #pragma unroll
    for (int i = 0; i < 16; i++) {
        int gr = row0 + rbase + i;
        if (gr < N_NODES) out[(size_t)gr * F + col] = fmaxf(acc[i], 0.f);
    }
}

// ---------------------------------------------------------------------------
extern "C" void kernel_launch(void* const* d_in, const int* in_sizes, int n_in,
                              void* d_out, int out_size) {
    const float* x    = (const float*)d_in[0];
    const void*  eidx = d_in[1];
    const float* Wl   = (const float*)d_in[2];
    const float* Wr   = (const float*)d_in[3];
    const float* b    = (const float*)d_in[4];
    float* out = (float*)d_out;

    cudaFuncSetAttribute(gemm_kernel, cudaFuncAttributeMaxDynamicSharedMemorySize,
                         (int)GEMM_SMEM);

    detect_kernel<<<1, 32>>>((const int*)eidx);
    zero_kernel<<<(N_NODES * F / 4) / 256, 256>>>();                    // 6250 blocks
    scatter_kernel<<<(N_EDGES * 32) / 256, 256>>>(eidx, x);             // 80000 blocks
    gemm_kernel<<<(N_NODES + GEMM_ROWS - 1) / GEMM_ROWS, GEMM_THREADS,
                  GEMM_SMEM>>>(x, Wl, Wr, b, out);
}

// round 2
// speedup vs baseline: 1.3910x; 1.3910x over previous
#include <cuda_runtime.h>
#include <cstdint>

#define N_NODES 50000
#define N_EDGES 640000
#define F 128
#define K_TOT 256

// Scratch (device globals — no runtime allocation allowed)
__device__ __align__(256) float g_summed[(size_t)N_NODES * F];   // 25.6 MB
__device__ __align__(256) float g_counts[N_NODES];
__device__ int g_idx64;

// ---------------------------------------------------------------------------
// Detect int64 vs int32 edge_index (JAX demotes to int32 w/o x64 mode).
// ---------------------------------------------------------------------------
__global__ void detect_kernel(const int* __restrict__ e) {
    if (threadIdx.x == 0) {
        int nz = 0;
        #pragma unroll 8
        for (int i = 0; i < 256; i++) nz |= e[2 * i + 1];
        g_idx64 = (nz == 0) ? 1 : 0;
    }
}

__global__ void zero_kernel() {
    int i = blockIdx.x * blockDim.x + threadIdx.x;   // 0 .. 1,599,999
    ((float4*)g_summed)[i] = make_float4(0.f, 0.f, 0.f, 0.f);
    if (i < N_NODES) g_counts[i] = 0.f;
}

// ---------------------------------------------------------------------------
// Scatter: one warp per edge, red.global.add.v4.f32 (REDG, no return).
// Near L2-traffic bound (~650MB through LTS); unchanged from R1.
// ---------------------------------------------------------------------------
__global__ void __launch_bounds__(256) scatter_kernel(const void* __restrict__ eidx,
                                                      const float* __restrict__ x) {
    int warp = (blockIdx.x * 256 + threadIdx.x) >> 5;
    int lane = threadIdx.x & 31;
    if (warp >= N_EDGES) return;

    int src, dst;
    if (g_idx64) {
        const long long* e = (const long long*)eidx;
        src = (int)e[warp];
        dst = (int)e[N_EDGES + warp];
    } else {
        const int* e = (const int*)eidx;
        src = e[warp];
        dst = e[N_EDGES + warp];
    }

    float4 v = ((const float4*)(x + (size_t)src * F))[lane];
    float* p = g_summed + (size_t)dst * F + lane * 4;
    asm volatile("red.global.add.v4.f32 [%0], {%1,%2,%3,%4};"
                 :: "l"(p), "f"(v.x), "f"(v.y), "f"(v.z), "f"(v.w)
                 : "memory");
    if (lane == 0) atomicAdd(&g_counts[dst], 1.0f);
}

// ---------------------------------------------------------------------------
// Fused GEMM: out = relu([mean | x] @ [W_l ; W_r] + b),  K = 256
//   - Combined W (256x128, 128 KB) fully smem-resident
//   - A staged per 32-wide K chunk (128 rows x 32 k = 16 KB), mean scaled inline
//   - 256 threads, 8x8 micro-tile per thread, fma.rn.f32x2 packed fp32
// ---------------------------------------------------------------------------
#define G_ROWS 128
#define G_THREADS 256
#define SW_ELEMS (K_TOT * F)            // 32768 floats = 128 KB
#define SA_ELEMS (G_ROWS * 32)          // 4096  floats = 16 KB
#define GEMM_SMEM ((SW_ELEMS + SA_ELEMS) * sizeof(float))  // 147456 B

#define FMA2(d, a, b) asm("fma.rn.f32x2 %0, %1, %2, %0;" : "+l"(d) : "l"(a), "l"(b))
#define DUP2(d, s)    asm("mov.b64 %0, {%1, %1};" : "=l"(d) : "f"(s))
#define PACK2(d, lo, hi)  asm("mov.b64 %0, {%1, %2};" : "=l"(d) : "f"(lo), "f"(hi))
#define UNPACK2(lo, hi, s) asm("mov.b64 {%0, %1}, %2;" : "=f"(lo), "=f"(hi) : "l"(s))

extern __shared__ float smem[];

__global__ void __launch_bounds__(G_THREADS, 1) gemm_kernel(
    const float* __restrict__ x,
    const float* __restrict__ Wl,
    const float* __restrict__ Wr,
    const float* __restrict__ b,
    float* __restrict__ out)
{
    float* sW = smem;                 // [256][128]
    float* sA = smem + SW_ELEMS;      // [128][32]
    __shared__ float sInv[G_ROWS];

    const int tid  = threadIdx.x;
    const int row0 = blockIdx.x * G_ROWS;

    // Stage combined W: rows 0..127 = W_l, 128..255 = W_r
    {
        const float4* wl4 = (const float4*)Wl;   // 4096 float4
        const float4* wr4 = (const float4*)Wr;
        float4* sw4 = (float4*)sW;
        #pragma unroll
        for (int i = tid; i < 4096; i += G_THREADS) {
            sw4[i]        = wl4[i];
            sw4[4096 + i] = wr4[i];
        }
    }
    if (tid < G_ROWS) {
        int gr = row0 + tid;
        float c = (gr < N_NODES) ? g_counts[gr] : 1.f;
        sInv[tid] = 1.f / fmaxf(c, 1.f);
    }

    const int tc  = tid & 15;        // col group 0..15
    const int tr  = tid >> 4;        // row group 0..15
    const int col = tc * 8;

    // Accumulators: 8 rows x 4 col-pairs, packed f32x2, init with bias
    uint64_t acc[8][4];
    {
        uint64_t bp[4];
        #pragma unroll
        for (int p = 0; p < 4; p++) {
            float b0 = b[col + 2 * p];
            float b1 = b[col + 2 * p + 1];
            PACK2(bp[p], b0, b1);
        }
        #pragma unroll
        for (int j = 0; j < 8; j++)
            #pragma unroll
            for (int p = 0; p < 4; p++) acc[j][p] = bp[p];
    }

    // K loop: 8 chunks of 32. Chunks 0..3 = mean (g_summed * inv), 4..7 = x.
    for (int kc = 0; kc < 8; kc++) {
        const bool isMean = (kc < 4);
        const float* src = isMean ? g_summed : x;
        const int c0 = (kc & 3) * 32;

        __syncthreads();
        // Stage A chunk: 128 rows x 8 float4 (coalesced)
        #pragma unroll
        for (int i = tid; i < G_ROWS * 8; i += G_THREADS) {
            int r  = i >> 3;
            int c4 = i & 7;
            int gr = row0 + r;
            float4 v = make_float4(0.f, 0.f, 0.f, 0.f);
            if (gr < N_NODES)
                v = ((const float4*)(src + (size_t)gr * F + c0))[c4];
            if (isMean) {
                float inv = sInv[r];
                v.x *= inv; v.y *= inv; v.z *= inv; v.w *= inv;
            }
            ((float4*)sA)[i] = v;
        }
        __syncthreads();

        const float* swbase = sW + (size_t)(kc * 32) * F + col;

        #pragma unroll 8
        for (int k = 0; k < 32; k++) {
            const float* wrow = swbase + k * F;
            uint64_t w[4];
            #pragma unroll
            for (int p = 0; p < 4; p++)
                w[p] = *(const uint64_t*)(wrow + 2 * p);

            uint64_t ad[8];
            #pragma unroll
            for (int j = 0; j < 8; j++) {
                float a = sA[(tr * 8 + j) * 32 + k];
                DUP2(ad[j], a);
            }
            #pragma unroll
            for (int j = 0; j < 8; j++)
                #pragma unroll
                for (int p = 0; p < 4; p++)
                    FMA2(acc[j][p], ad[j], w[p]);
        }
    }

    // Epilogue: relu + store (two float4 per row)
    #pragma unroll
    for (int j = 0; j < 8; j++) {
        int gr = row0 + tr * 8 + j;
        if (gr >= N_NODES) continue;
        float v[8];
        #pragma unroll
        for (int p = 0; p < 4; p++) {
            float lo, hi;
            UNPACK2(lo, hi, acc[j][p]);
            v[2 * p]     = fmaxf(lo, 0.f);
            v[2 * p + 1] = fmaxf(hi, 0.f);
        }
        float4* o = (float4*)(out + (size_t)gr * F + col);
        o[0] = make_float4(v[0], v[1], v[2], v[3]);
        o[1] = make_float4(v[4], v[5], v[6], v[7]);
    }
}

// ---------------------------------------------------------------------------
extern "C" void kernel_launch(void* const* d_in, const int* in_sizes, int n_in,
                              void* d_out, int out_size) {
    const float* x    = (const float*)d_in[0];
    const void*  eidx = d_in[1];
    const float* Wl   = (const float*)d_in[2];
    const float* Wr   = (const float*)d_in[3];
    const float* b    = (const float*)d_in[4];
    float* out = (float*)d_out;

    cudaFuncSetAttribute(gemm_kernel, cudaFuncAttributeMaxDynamicSharedMemorySize,
                         (int)GEMM_SMEM);

    detect_kernel<<<1, 32>>>((const int*)eidx);
    zero_kernel<<<(N_NODES * F / 4) / 256, 256>>>();
    scatter_kernel<<<(N_EDGES * 32) / 256, 256>>>(eidx, x);
    gemm_kernel<<<(N_NODES + G_ROWS - 1) / G_ROWS, G_THREADS, GEMM_SMEM>>>(
        x, Wl, Wr, b, out);
}